// round 8
// baseline (speedup 1.0000x reference)
#include <cuda_runtime.h>
#include <cuda_fp16.h>
#include <cstdint>

// Problem constants (fixed by the dataset)
#define BROWS   32768
#define MDIM    512
#define HDIM    256
#define TOTROWS (2 * BROWS)   // both branches stacked

// ---------------------------------------------------------------------------
// Scratch (static device allocations — no cudaMalloc allowed)
// ---------------------------------------------------------------------------
// Activations: u16 per element = (byte0 = hi digit a1, byte1 = lo digit a0)
__device__ __align__(16) uint16_t g_x8 [(size_t)BROWS * MDIM];
__device__ __align__(16) uint16_t g_xc8[(size_t)BROWS * MDIM];
__device__ __align__(16) float    g_xs [16 * (size_t)BROWS];   // [kblk][row]
__device__ __align__(16) float    g_xcs[16 * (size_t)BROWS];
__device__ __align__(16) uint16_t g_a8_0[(size_t)TOTROWS * HDIM];
__device__ __align__(16) float    g_as_0[8 * (size_t)TOTROWS];
__device__ __align__(16) uint16_t g_a8_1[(size_t)TOTROWS * HDIM];
__device__ __align__(16) float    g_as_1[8 * (size_t)TOTROWS];
// Weights: digit fragment-major (R7 layout), per-column scales
__device__ __align__(16) uint32_t g_W8_0[(size_t)MDIM * 128];
__device__ __align__(16) uint32_t g_W8_H[5][(size_t)HDIM * 128];
__device__ float g_sW[6][HDIM];

// ---------------------------------------------------------------------------
// Helpers
// ---------------------------------------------------------------------------
__device__ __forceinline__ uint32_t smem_u32(const void* p) {
    uint32_t a;
    asm("{ .reg .u64 t; cvta.to.shared.u64 t, %1; cvt.u32.u64 %0, t; }"
        : "=r"(a) : "l"(p));
    return a;
}
// s8 in, s32 accum, k32
__device__ __forceinline__ void mma_s8(int* d, const uint32_t* a,
                                       uint32_t b0, uint32_t b1) {
    asm volatile(
        "mma.sync.aligned.m16n8k32.row.col.s32.s8.s8.s32 "
        "{%0,%1,%2,%3}, {%4,%5,%6,%7}, {%8,%9}, {%0,%1,%2,%3};"
        : "+r"(d[0]), "+r"(d[1]), "+r"(d[2]), "+r"(d[3])
        : "r"(a[0]), "r"(a[1]), "r"(a[2]), "r"(a[3]), "r"(b0), "r"(b1));
}
#define CP_ASYNC16(dst, src) \
    asm volatile("cp.async.cg.shared.global [%0], [%1], 16;" :: "r"(dst), "l"(src))
#define CP_COMMIT() asm volatile("cp.async.commit_group;" ::: "memory")
#define CP_WAIT0()  asm volatile("cp.async.wait_group 0;" ::: "memory")

// quantize v against inv = 16000/blockmax -> u16 (byte0 = a1, byte1 = a0)
__device__ __forceinline__ uint32_t q16(float v, float inv) {
    int ai = __float2int_rn(v * inv);
    int a1 = (ai + 64) >> 7;
    int a0 = ai - (a1 << 7);
    return (uint32_t)(a1 & 0xff) | ((uint32_t)(a0 & 0xff) << 8);
}

// ---------------------------------------------------------------------------
// Corruption kernel (rank-q logic validated rel_err = 0.0 since R1);
// emits int8-digit planes + per-(row,32-block) scales for x and xc.
// ---------------------------------------------------------------------------
__global__ void __launch_bounds__(256) corrupt_kernel(
    const float* __restrict__ x, const float* __restrict__ u,
    const float* __restrict__ r, const float* __restrict__ low,
    const float* __restrict__ high, const int* __restrict__ qptr, int qdef,
    uint16_t* __restrict__ x8, float* __restrict__ xs,
    uint16_t* __restrict__ xc8, float* __restrict__ xcs)
{
    __shared__ float us[MDIM];
    __shared__ int   hist[1024];
    __shared__ int   s_bin, s_rank, s_cnt;
    __shared__ unsigned long long cand[48];
    __shared__ unsigned long long s_thresh;

    const int row = blockIdx.x;
    const int tid = threadIdx.x;
    const size_t base = (size_t)row * MDIM;

    int q = qptr ? *qptr : qdef;

    for (int j = tid; j < MDIM; j += 256) us[j] = u[base + j];
    for (int j = tid; j < 1024; j += 256) hist[j] = 0;
    __syncthreads();

    if (q <= 0) {
        if (tid == 0) s_thresh = 0ULL;
    } else if (q >= MDIM) {
        if (tid == 0) s_thresh = ~0ULL;
    }

    if (q > 0 && q < MDIM) {
        for (int j = tid; j < MDIM; j += 256) {
            float v = us[j];
            int b = (int)(v * 1024.0f);
            b = b < 0 ? 0 : (b > 1023 ? 1023 : b);
            atomicAdd(&hist[b], 1);
        }
        __syncthreads();

        if (tid < 32) {
            int s = 0;
            const int b0 = tid * 32;
            #pragma unroll
            for (int b = 0; b < 32; b++) s += hist[b0 + b];
            int pre = s;
            #pragma unroll
            for (int o = 1; o < 32; o <<= 1) {
                int n = __shfl_up_sync(0xffffffffu, pre, o);
                if (tid >= o) pre += n;
            }
            int excl = pre - s;
            if (q >= excl && q < excl + s) {
                int c = excl;
                for (int b = b0; b < b0 + 32; b++) {
                    int h = hist[b];
                    if (q < c + h) { s_bin = b; s_rank = q - c; break; }
                    c += h;
                }
            }
            if (tid == 0) s_cnt = 0;
        }
        __syncthreads();

        const int bsel = s_bin;
        for (int j = tid; j < MDIM; j += 256) {
            float v = us[j];
            int b = (int)(v * 1024.0f);
            b = b < 0 ? 0 : (b > 1023 ? 1023 : b);
            if (b == bsel) {
                int idx = atomicAdd(&s_cnt, 1);
                if (idx < 48)
                    cand[idx] = ((unsigned long long)__float_as_uint(v) << 9)
                                | (unsigned)j;
            }
        }
        __syncthreads();

        if (tid == 0) {
            int cnt = s_cnt < 48 ? s_cnt : 48;
            int rk = s_rank;
            unsigned long long th = 0ULL;
            for (int i = 0; i < cnt; i++) {
                int c = 0;
                for (int k2 = 0; k2 < cnt; k2++) c += (cand[k2] < cand[i]);
                if (c == rk) th = cand[i];
            }
            s_thresh = th;
        }
    }
    __syncthreads();

    const unsigned long long th = s_thresh;
    const int j0 = tid * 2, j1 = j0 + 1;
    float v0 = us[j0], v1 = us[j1];
    unsigned long long k0 =
        ((unsigned long long)__float_as_uint(v0) << 9) | (unsigned)j0;
    unsigned long long k1 =
        ((unsigned long long)__float_as_uint(v1) << 9) | (unsigned)j1;
    float xv0 = x[base + j0], xv1 = x[base + j1];
    float xr0 = low[j0] + (high[j0] - low[j0]) * r[base + j0];
    float xr1 = low[j1] + (high[j1] - low[j1]) * r[base + j1];
    float xc0 = (k0 < th) ? xr0 : xv0;
    float xc1 = (k1 < th) ? xr1 : xv1;

    // per-(row, 32-feature block) max; block = 16 consecutive threads
    float bmx = fmaxf(fabsf(xv0), fabsf(xv1));
    float bmc = fmaxf(fabsf(xc0), fabsf(xc1));
    #pragma unroll
    for (int o = 1; o < 16; o <<= 1) {
        bmx = fmaxf(bmx, __shfl_xor_sync(0xffffffffu, bmx, o));
        bmc = fmaxf(bmc, __shfl_xor_sync(0xffffffffu, bmc, o));
    }
    float invx = bmx > 1e-20f ? 16000.0f / bmx : 0.0f;
    float invc = bmc > 1e-20f ? 16000.0f / bmc : 0.0f;

    *(uint32_t*)(x8 + base + j0)  = q16(xv0, invx) | (q16(xv1, invx) << 16);
    *(uint32_t*)(xc8 + base + j0) = q16(xc0, invc) | (q16(xc1, invc) << 16);

    if ((tid & 15) == 0) {
        int blk = tid >> 4;   // 0..15
        xs [blk * BROWS + row] = bmx * (1.0f / 16000.0f);
        xcs[blk * BROWS + row] = bmc * (1.0f / 16000.0f);
    }
}

// ---------------------------------------------------------------------------
// Weight column-max -> per-column scale sW[n] = colmax/16000
// ---------------------------------------------------------------------------
__global__ void __launch_bounds__(128) colmax_kernel(
    const float* __restrict__ W, int K, float* __restrict__ sW)
{
    __shared__ float red[128];
    int n = blockIdx.x;
    float m = 0.0f;
    for (int k = threadIdx.x; k < K; k += 128)
        m = fmaxf(m, fabsf(W[(size_t)k * HDIM + n]));
    red[threadIdx.x] = m;
    __syncthreads();
    for (int s = 64; s > 0; s >>= 1) {
        if (threadIdx.x < s)
            red[threadIdx.x] = fmaxf(red[threadIdx.x], red[threadIdx.x + s]);
        __syncthreads();
    }
    if (threadIdx.x == 0) sW[n] = red[0] * (1.0f / 16000.0f);
}

// ---------------------------------------------------------------------------
// Weight digit pack: frag-major (R7-validated geometry for m16n8k32 B):
// u32 idx = ((c*32+nf)*32+lane)*4 + q ; q: 0=hi r0, 1=hi r1, 2=lo r0, 3=lo r1
// reg r covers k = c*32 + r*16 + (lane&3)*4 + (0..3); col n = nf*8 + (lane>>2)
// ---------------------------------------------------------------------------
__global__ void __launch_bounds__(256) pack_w8_kernel(
    const float* __restrict__ W, const float* __restrict__ sW,
    uint32_t* __restrict__ W8, int K)
{
    int idx = blockIdx.x * 256 + threadIdx.x;   // over K*128
    if (idx >= K * 128) return;
    int q    = idx & 3;
    int lane = (idx >> 2) & 31;
    int nf   = (idx >> 7) & 31;
    int c    = idx >> 12;
    int r     = q & 1;
    int digit = q >> 1;    // 0 = hi (w1), 1 = lo (w0)
    int n  = nf * 8 + (lane >> 2);
    int k0 = c * 32 + r * 16 + (lane & 3) * 4;

    float inv = 1.0f / sW[n];   // = 16000/colmax
    uint32_t out = 0;
    #pragma unroll
    for (int j = 0; j < 4; j++) {
        float w = W[(size_t)(k0 + j) * HDIM + n];
        int wi = __float2int_rn(w * inv);
        int w1 = (wi + 64) >> 7;
        int w0 = wi - (w1 << 7);
        int d = digit ? w0 : w1;
        out |= (uint32_t)(d & 0xff) << (8 * j);
    }
    W8[idx] = out;
}

// ---------------------------------------------------------------------------
// int8 split GEMM: C[128x64 tile of 256] = A @ W + bias
// Per chunk per m16n8 tile: 3 IMMA k32 (a1w1; a1w0+a0w1), exact s32, fold
// per chunk with per-(row,chunk) A scale. Per-col W scale in epilogue.
// 8 warps (4m x 2n), warp tile 32x32, double-buffered cp.async.
// ---------------------------------------------------------------------------
#define OFF_A8 0
#define OFF_B8 8192
#define OFF_SA 12288
#define STAGE  12800
#define DSMEM_SZ (2 * STAGE + 512)

template <int K, bool RELU, bool PACKOUT>
__global__ void __launch_bounds__(256, 2) gemm_i8(
    const uint16_t* __restrict__ A8, const float* __restrict__ As, int sArows,
    const uint16_t* __restrict__ A28, const float* __restrict__ A2s,
    int rowsA,
    const uint32_t* __restrict__ W8, const float* __restrict__ sW,
    const float* __restrict__ bias,
    uint16_t* __restrict__ C8, float* __restrict__ Cs,
    float* __restrict__ Cf)
{
    extern __shared__ __align__(16) char dsm[];
    const int tid  = threadIdx.x;
    const int lane = tid & 31;
    const int wid  = tid >> 5;
    const int wm   = wid >> 1;     // 0..3, 32 rows
    const int wn   = wid & 1;      // 0..1, 32 cols
    const int g8   = lane >> 2;
    const int tg   = lane & 3;

    const int row0 = blockIdx.y * 128;
    const int col0 = blockIdx.x * 64;
    const int nf0  = blockIdx.x * 8;

    const uint32_t base = smem_u32(dsm);
    float* s_bias = (float*)(dsm + 2 * STAGE);
    float* s_sw   = (float*)(dsm + 2 * STAGE + 256);

    const uint16_t* Aq = A8;
    const float*    Sq = As;
    int rb = row0;
    if (A28 != nullptr && row0 >= rowsA) { Aq = A28; Sq = A2s; rb = row0 - rowsA; }
    const uint16_t* A8g = Aq + (size_t)rb * K;

    if (tid < 64) { s_bias[tid] = bias[col0 + tid]; s_sw[tid] = sW[col0 + tid]; }

    const int NC = K / 32;

    auto issue = [&](int c, int buf) {
        const uint32_t sb = base + buf * STAGE;
        // A digits: 128 rows x 64B, XOR-swizzled (R7-validated)
        #pragma unroll
        for (int i = 0; i < 2; i++) {
            int w = tid + i * 256;
            int m = w >> 2, uu = w & 3;
            CP_ASYNC16(sb + OFF_A8 + m * 64 + ((uu ^ (m & 3)) << 4),
                       A8g + (size_t)m * K + c * 32 + uu * 8);
        }
        // B digits: 8 nf x 32 lane units
        {
            size_t gi = (((size_t)c * 32 + nf0 + (tid >> 5)) * 32 + (tid & 31)) * 4;
            CP_ASYNC16(sb + OFF_B8 + tid * 16, W8 + gi);
        }
        // A scales for this chunk: 128 contiguous floats
        if (tid < 32) {
            CP_ASYNC16(sb + OFF_SA + tid * 16,
                       Sq + (size_t)c * sArows + rb + tid * 4);
        }
    };

    issue(0, 0);
    CP_COMMIT();
    CP_WAIT0();
    __syncthreads();

    float facc[2][4][4];
    #pragma unroll
    for (int mi = 0; mi < 2; mi++)
        #pragma unroll
        for (int ni = 0; ni < 4; ni++)
            #pragma unroll
            for (int j = 0; j < 4; j++) facc[mi][ni][j] = 0.0f;

    for (int c = 0; c < NC; c++) {
        const int cur = c & 1;
        if (c + 1 < NC) { issue(c + 1, cur ^ 1); CP_COMMIT(); }
        const uint32_t sb = base + cur * STAGE;

        // per-chunk A scales (x128 folded)
        float sa128[2][2];
        #pragma unroll
        for (int mi = 0; mi < 2; mi++)
            #pragma unroll
            for (int ri = 0; ri < 2; ri++) {
                float s;
                uint32_t ad = sb + OFF_SA
                    + (uint32_t)((wm * 32 + mi * 16 + g8 + ri * 8) * 4);
                asm volatile("ld.shared.f32 %0, [%1];" : "=f"(s) : "r"(ad));
                sa128[mi][ri] = s * 128.0f;
            }

        // A fragments: a1 (hi) and a0 (lo) digit planes (R7-validated)
        uint32_t a1[2][4], a0[2][4];
        #pragma unroll
        for (int mi = 0; mi < 2; mi++) {
            #pragma unroll
            for (int kh = 0; kh < 2; kh++) {
                #pragma unroll
                for (int ri = 0; ri < 2; ri++) {
                    int m = wm * 32 + mi * 16 + g8 + ri * 8;
                    uint32_t addr = sb + OFF_A8 + m * 64
                        + (((((tg >> 1) + kh * 2) ^ (m & 3)) << 4))
                        + ((tg & 1) << 3);
                    uint32_t w0, w1;
                    asm volatile("ld.shared.v2.b32 {%0,%1}, [%2];"
                                 : "=r"(w0), "=r"(w1) : "r"(addr));
                    a1[mi][ri + 2 * kh] = __byte_perm(w0, w1, 0x6420);
                    a0[mi][ri + 2 * kh] = __byte_perm(w0, w1, 0x7531);
                }
            }
        }

        #pragma unroll
        for (int ni = 0; ni < 4; ni++) {
            const uint32_t boff =
                (uint32_t)((((wn * 4 + ni) * 32 + lane)) * 16);
            uint32_t b8[4];   // {w1 r0, w1 r1, w0 r0, w0 r1}
            asm volatile("ld.shared.v4.b32 {%0,%1,%2,%3}, [%4];"
                         : "=r"(b8[0]), "=r"(b8[1]), "=r"(b8[2]), "=r"(b8[3])
                         : "r"(sb + OFF_B8 + boff));
            #pragma unroll
            for (int mi = 0; mi < 2; mi++) {
                int hh[4] = {0, 0, 0, 0};
                int mx[4] = {0, 0, 0, 0};
                mma_s8(hh, a1[mi], b8[0], b8[1]);   // a1*w1
                mma_s8(mx, a1[mi], b8[2], b8[3]);   // a1*w0
                mma_s8(mx, a0[mi], b8[0], b8[1]);   // + a0*w1
                #pragma unroll
                for (int j = 0; j < 4; j++) {
                    int tot = hh[j] * 128 + mx[j];  // exact, <2^27
                    facc[mi][ni][j] =
                        fmaf((float)tot, sa128[mi][j >> 1], facc[mi][ni][j]);
                }
            }
        }

        if (c + 1 < NC) { CP_WAIT0(); __syncthreads(); }
    }

    // ---- epilogue ----
    const int nblk = blockIdx.x * 2 + wn;
    #pragma unroll
    for (int mi = 0; mi < 2; mi++) {
        const int r0 = row0 + wm * 32 + mi * 16 + g8;
        const int r1 = r0 + 8;
        float v[4][4];
        #pragma unroll
        for (int ni = 0; ni < 4; ni++) {
            const int nl = wn * 32 + ni * 8 + tg * 2;
            const float sw0 = s_sw[nl], sw1 = s_sw[nl + 1];
            const float b0 = s_bias[nl], b1 = s_bias[nl + 1];
            v[ni][0] = facc[mi][ni][0] * sw0 + b0;
            v[ni][1] = facc[mi][ni][1] * sw1 + b1;
            v[ni][2] = facc[mi][ni][2] * sw0 + b0;
            v[ni][3] = facc[mi][ni][3] * sw1 + b1;
            if (RELU) {
                #pragma unroll
                for (int j = 0; j < 4; j++) v[ni][j] = fmaxf(v[ni][j], 0.0f);
            }
        }
        if (PACKOUT) {
            float bm0 = 0.0f, bm1 = 0.0f;
            #pragma unroll
            for (int ni = 0; ni < 4; ni++) {
                bm0 = fmaxf(bm0, fmaxf(fabsf(v[ni][0]), fabsf(v[ni][1])));
                bm1 = fmaxf(bm1, fmaxf(fabsf(v[ni][2]), fabsf(v[ni][3])));
            }
            #pragma unroll
            for (int o = 1; o < 4; o <<= 1) {
                bm0 = fmaxf(bm0, __shfl_xor_sync(0xffffffffu, bm0, o));
                bm1 = fmaxf(bm1, __shfl_xor_sync(0xffffffffu, bm1, o));
            }
            float inv0 = bm0 > 1e-20f ? 16000.0f / bm0 : 0.0f;
            float inv1 = bm1 > 1e-20f ? 16000.0f / bm1 : 0.0f;
            if (tg == 0) {
                Cs[(size_t)nblk * TOTROWS + r0] = bm0 * (1.0f / 16000.0f);
                Cs[(size_t)nblk * TOTROWS + r1] = bm1 * (1.0f / 16000.0f);
            }
            #pragma unroll
            for (int ni = 0; ni < 4; ni++) {
                const int nl = col0 + wn * 32 + ni * 8 + tg * 2;
                *(uint32_t*)(C8 + (size_t)r0 * HDIM + nl) =
                    q16(v[ni][0], inv0) | (q16(v[ni][1], inv0) << 16);
                *(uint32_t*)(C8 + (size_t)r1 * HDIM + nl) =
                    q16(v[ni][2], inv1) | (q16(v[ni][3], inv1) << 16);
            }
        } else {
            #pragma unroll
            for (int ni = 0; ni < 4; ni++) {
                const int nl = col0 + wn * 32 + ni * 8 + tg * 2;
                *(float2*)(Cf + (size_t)r0 * HDIM + nl) =
                    make_float2(v[ni][0], v[ni][1]);
                *(float2*)(Cf + (size_t)r1 * HDIM + nl) =
                    make_float2(v[ni][2], v[ni][3]);
            }
        }
    }
}

// ---------------------------------------------------------------------------
// Launch
// ---------------------------------------------------------------------------
extern "C" void kernel_launch(void* const* d_in, const int* in_sizes, int n_in,
                              void* d_out, int out_size)
{
    const float *x = 0, *u = 0, *r = 0, *low = 0, *high = 0, *We0 = 0;
    const int* qptr = 0;
    const float* W65[8];  int nW = 0;
    const float* b256[8]; int nB = 0;

    for (int i = 0; i < n_in; i++) {
        int s = in_sizes[i];
        const float* p = (const float*)d_in[i];
        if (s == BROWS * MDIM) {
            if (!x) x = p; else if (!u) u = p; else if (!r) r = p;
        } else if (s == MDIM) {
            if (!low) low = p; else if (!high) high = p;
        } else if (s == 1) {
            qptr = (const int*)d_in[i];
        } else if (s == MDIM * HDIM) {
            We0 = p;
        } else if (s == HDIM * HDIM) {
            if (nW < 8) W65[nW++] = p;
        } else if (s == HDIM) {
            if (nB < 8) b256[nB++] = p;
        }
    }
    const float* bl[6] = {b256[0], b256[1], b256[2], b256[3], b256[4], b256[5]};

    uint16_t *x8 = 0, *xc8 = 0, *a8_0 = 0, *a8_1 = 0;
    float *xs = 0, *xcs = 0, *as_0 = 0, *as_1 = 0, *sWall = 0;
    uint32_t *w8_0 = 0, *w8_H = 0;
    cudaGetSymbolAddress((void**)&x8,   g_x8);
    cudaGetSymbolAddress((void**)&xs,   g_xs);
    cudaGetSymbolAddress((void**)&xc8,  g_xc8);
    cudaGetSymbolAddress((void**)&xcs,  g_xcs);
    cudaGetSymbolAddress((void**)&a8_0, g_a8_0);
    cudaGetSymbolAddress((void**)&as_0, g_as_0);
    cudaGetSymbolAddress((void**)&a8_1, g_a8_1);
    cudaGetSymbolAddress((void**)&as_1, g_as_1);
    cudaGetSymbolAddress((void**)&w8_0, g_W8_0);
    cudaGetSymbolAddress((void**)&w8_H, g_W8_H);
    cudaGetSymbolAddress((void**)&sWall, g_sW);
    float* out = (float*)d_out;

    const size_t WHPL = (size_t)HDIM * 128;
    auto w8 = [&](int i) { return w8_H + (size_t)i * WHPL; };
    auto sw = [&](int i) { return sWall + (size_t)i * HDIM; };   // layer scale row

    // 1) corruption + digit/scale emit
    corrupt_kernel<<<BROWS, 256>>>(x, u, r, low, high, qptr, 307,
                                   x8, xs, xc8, xcs);

    // 2) weight scales + digit packing (tiny)
    colmax_kernel<<<HDIM, 128>>>(We0, MDIM, sw(0));
    pack_w8_kernel<<<(MDIM * 128) / 256, 256>>>(We0, sw(0), w8_0, MDIM);
    for (int i = 0; i < 5; i++) {
        colmax_kernel<<<HDIM, 128>>>(W65[i], HDIM, sw(i + 1));
        pack_w8_kernel<<<(HDIM * 128) / 256, 256>>>(W65[i], sw(i + 1), w8(i), HDIM);
    }

    // 3) 6 layers on int8 IMMA tensor cores, both branches stacked
    dim3 grid(HDIM / 64, TOTROWS / 128);   // (4, 512)
    dim3 blk(256);
    const uint16_t* N8 = (const uint16_t*)0;
    const float* NS = (const float*)0;

    gemm_i8<MDIM, true,  true ><<<grid, blk, DSMEM_SZ>>>(
        x8, xs, BROWS, xc8, xcs, BROWS, w8_0, sw(0), bl[0],
        a8_0, as_0, (float*)0);
    gemm_i8<HDIM, true,  true ><<<grid, blk, DSMEM_SZ>>>(
        a8_0, as_0, TOTROWS, N8, NS, TOTROWS, w8(0), sw(1), bl[1],
        a8_1, as_1, (float*)0);
    gemm_i8<HDIM, true,  true ><<<grid, blk, DSMEM_SZ>>>(
        a8_1, as_1, TOTROWS, N8, NS, TOTROWS, w8(1), sw(2), bl[2],
        a8_0, as_0, (float*)0);
    gemm_i8<HDIM, false, true ><<<grid, blk, DSMEM_SZ>>>(
        a8_0, as_0, TOTROWS, N8, NS, TOTROWS, w8(2), sw(3), bl[3],
        a8_1, as_1, (float*)0);
    gemm_i8<HDIM, true,  true ><<<grid, blk, DSMEM_SZ>>>(
        a8_1, as_1, TOTROWS, N8, NS, TOTROWS, w8(3), sw(4), bl[4],
        a8_0, as_0, (float*)0);
    gemm_i8<HDIM, false, false><<<grid, blk, DSMEM_SZ>>>(
        a8_0, as_0, TOTROWS, N8, NS, TOTROWS, w8(4), sw(5), bl[5],
        (uint16_t*)0, (float*)0, out);

    (void)out_size;
}

// round 9
// speedup vs baseline: 2.9596x; 2.9596x over previous
#include <cuda_runtime.h>
#include <cuda_fp16.h>
#include <cstdint>

// Problem constants (fixed by the dataset)
#define BROWS   32768
#define MDIM    512
#define HDIM    256
#define TOTROWS (2 * BROWS)   // both branches stacked

// ---------------------------------------------------------------------------
// Scratch (static device allocations — no cudaMalloc allowed)
// ---------------------------------------------------------------------------
__device__ __align__(16) __half g_x16 [(size_t)BROWS * MDIM];
__device__ __align__(16) __half g_xc16[(size_t)BROWS * MDIM];
__device__ __align__(16) __half g_a0  [(size_t)TOTROWS * HDIM];
__device__ __align__(16) __half g_a1  [(size_t)TOTROWS * HDIM];
// Weights: fp16 fragment-major planes hi + lo (u32 = 2 fp16 along k)
__device__ __align__(16) uint32_t g_W0p[2][(size_t)MDIM * 128];
__device__ __align__(16) uint32_t g_WHp[5][2][(size_t)HDIM * 128];

// ---------------------------------------------------------------------------
// Helpers
// ---------------------------------------------------------------------------
__device__ __forceinline__ uint32_t smem_u32(const void* p) {
    uint32_t a;
    asm("{ .reg .u64 t; cvta.to.shared.u64 t, %1; cvt.u32.u64 %0, t; }"
        : "=r"(a) : "l"(p));
    return a;
}
__device__ __forceinline__ void mma_f16(float* d, const uint32_t* a,
                                        uint32_t b0, uint32_t b1) {
    asm volatile(
        "mma.sync.aligned.m16n8k16.row.col.f32.f16.f16.f32 "
        "{%0,%1,%2,%3}, {%4,%5,%6,%7}, {%8,%9}, {%0,%1,%2,%3};"
        : "+f"(d[0]), "+f"(d[1]), "+f"(d[2]), "+f"(d[3])
        : "r"(a[0]), "r"(a[1]), "r"(a[2]), "r"(a[3]), "r"(b0), "r"(b1));
}
__device__ __forceinline__ void ldsm4(uint32_t* r, uint32_t addr) {
    asm volatile("ldmatrix.sync.aligned.m8n8.x4.shared.b16 {%0,%1,%2,%3}, [%4];"
                 : "=r"(r[0]), "=r"(r[1]), "=r"(r[2]), "=r"(r[3]) : "r"(addr));
}
#define CP_ASYNC16(dst, src) \
    asm volatile("cp.async.cg.shared.global [%0], [%1], 16;" :: "r"(dst), "l"(src))
#define CP_COMMIT() asm volatile("cp.async.commit_group;" ::: "memory")
#define CP_WAIT0()  asm volatile("cp.async.wait_group 0;" ::: "memory")

__device__ __forceinline__ void split2(float v, __half& h, __half& l) {
    h = __float2half_rn(v);
    l = __float2half_rn(v - __half2float(h));
}
__device__ __forceinline__ uint32_t pack2h(__half a, __half b) {
    return (uint32_t)__half_as_ushort(a) |
           ((uint32_t)__half_as_ushort(b) << 16);
}

// ---------------------------------------------------------------------------
// Corruption kernel (rank-q logic validated rel_err = 0.0 since R1);
// emits plain fp16 planes for x and xc.
// ---------------------------------------------------------------------------
__global__ void __launch_bounds__(256) corrupt_kernel(
    const float* __restrict__ x, const float* __restrict__ u,
    const float* __restrict__ r, const float* __restrict__ low,
    const float* __restrict__ high, const int* __restrict__ qptr, int qdef,
    __half* __restrict__ x16, __half* __restrict__ xc16)
{
    __shared__ float us[MDIM];
    __shared__ int   hist[1024];
    __shared__ int   s_bin, s_rank, s_cnt;
    __shared__ unsigned long long cand[48];
    __shared__ unsigned long long s_thresh;

    const int row = blockIdx.x;
    const int tid = threadIdx.x;
    const size_t base = (size_t)row * MDIM;

    int q = qptr ? *qptr : qdef;

    for (int j = tid; j < MDIM; j += 256) us[j] = u[base + j];
    for (int j = tid; j < 1024; j += 256) hist[j] = 0;
    __syncthreads();

    if (q <= 0) {
        if (tid == 0) s_thresh = 0ULL;
    } else if (q >= MDIM) {
        if (tid == 0) s_thresh = ~0ULL;
    }

    if (q > 0 && q < MDIM) {
        for (int j = tid; j < MDIM; j += 256) {
            float v = us[j];
            int b = (int)(v * 1024.0f);
            b = b < 0 ? 0 : (b > 1023 ? 1023 : b);
            atomicAdd(&hist[b], 1);
        }
        __syncthreads();

        if (tid < 32) {
            int s = 0;
            const int b0 = tid * 32;
            #pragma unroll
            for (int b = 0; b < 32; b++) s += hist[b0 + b];
            int pre = s;
            #pragma unroll
            for (int o = 1; o < 32; o <<= 1) {
                int n = __shfl_up_sync(0xffffffffu, pre, o);
                if (tid >= o) pre += n;
            }
            int excl = pre - s;
            if (q >= excl && q < excl + s) {
                int c = excl;
                for (int b = b0; b < b0 + 32; b++) {
                    int h = hist[b];
                    if (q < c + h) { s_bin = b; s_rank = q - c; break; }
                    c += h;
                }
            }
            if (tid == 0) s_cnt = 0;
        }
        __syncthreads();

        const int bsel = s_bin;
        for (int j = tid; j < MDIM; j += 256) {
            float v = us[j];
            int b = (int)(v * 1024.0f);
            b = b < 0 ? 0 : (b > 1023 ? 1023 : b);
            if (b == bsel) {
                int idx = atomicAdd(&s_cnt, 1);
                if (idx < 48)
                    cand[idx] = ((unsigned long long)__float_as_uint(v) << 9)
                                | (unsigned)j;
            }
        }
        __syncthreads();

        if (tid == 0) {
            int cnt = s_cnt < 48 ? s_cnt : 48;
            int rk = s_rank;
            unsigned long long th = 0ULL;
            for (int i = 0; i < cnt; i++) {
                int c = 0;
                for (int k2 = 0; k2 < cnt; k2++) c += (cand[k2] < cand[i]);
                if (c == rk) th = cand[i];
            }
            s_thresh = th;
        }
    }
    __syncthreads();

    const unsigned long long th = s_thresh;
    const int j0 = tid * 2, j1 = j0 + 1;
    float v0 = us[j0], v1 = us[j1];
    unsigned long long k0 =
        ((unsigned long long)__float_as_uint(v0) << 9) | (unsigned)j0;
    unsigned long long k1 =
        ((unsigned long long)__float_as_uint(v1) << 9) | (unsigned)j1;
    float xv0 = x[base + j0], xv1 = x[base + j1];
    float xr0 = low[j0] + (high[j0] - low[j0]) * r[base + j0];
    float xr1 = low[j1] + (high[j1] - low[j1]) * r[base + j1];
    float xc0 = (k0 < th) ? xr0 : xv0;
    float xc1 = (k1 < th) ? xr1 : xv1;

    *(uint32_t*)(x16 + base + j0) =
        pack2h(__float2half_rn(xv0), __float2half_rn(xv1));
    *(uint32_t*)(xc16 + base + j0) =
        pack2h(__float2half_rn(xc0), __float2half_rn(xc1));
}

// ---------------------------------------------------------------------------
// Weight pack: W[K,256] -> fp16 B-fragment planes (hi, lo), v4-grouped.
// Geometry validated in R5: u32 idx = (((c*2+ks)*16+nfp)*32+lane)*4 + reg4
//   c=k/32, ks=(k/16)&1, rem=k%16: b01=rem/8, tig=(rem%8)/2 (k-pair, even low)
//   nf=n/8, nfp=nf/2, reg4=(nf&1)*2+b01, lane=(n%8)*4+tig
// ---------------------------------------------------------------------------
__global__ void __launch_bounds__(256) pack_w_kernel(
    const float* __restrict__ W, uint32_t* __restrict__ WfHi,
    uint32_t* __restrict__ WfLo, int K)
{
    int idx = blockIdx.x * 256 + threadIdx.x;   // over (K/2)*256
    if (idx >= (K / 2) * HDIM) return;
    int k2 = idx >> 8;
    int n  = idx & 255;
    int k  = k2 * 2;
    __half h0, l0, h1, l1;
    split2(W[(size_t)k * HDIM + n], h0, l0);
    split2(W[(size_t)(k + 1) * HDIM + n], h1, l1);

    int c = k >> 5, ks = (k >> 4) & 1, rem = k & 15;
    int b01 = rem >> 3, tig = (rem & 7) >> 1;
    int nf = n >> 3, nfp = nf >> 1;
    int reg4 = ((nf & 1) << 1) | b01;
    int lane = ((n & 7) << 2) | tig;
    size_t i32 = ((((size_t)c * 2 + ks) * 16 + nfp) * 32 + lane) * 4 + reg4;
    WfHi[i32] = pack2h(h0, h1);
    WfLo[i32] = pack2h(l0, l1);
}

// ---------------------------------------------------------------------------
// fp16 split-2 GEMM: C[128x128 tile of 256] = A @ (Whi + Wlo) + bias
// A: plain fp16 row-major (single plane). 2 MMA per m16n8k16 tile.
// 8 warps (4m x 2n), warp tile 32x64, BK=32, double-buffered cp.async,
// ldmatrix.x4 A (80B rows), lds.128 B (2 n-frags/load). (R5 geometry.)
// ---------------------------------------------------------------------------
#define OFF_A   0
#define OFF_BHI 10240
#define OFF_BLO 18432
#define STAGE_B 26624
#define DSMEM_SZ (2 * STAGE_B + 512)

template <int K, bool RELU, bool PACKOUT>
__global__ void __launch_bounds__(256, 2) gemm_f16x2(
    const __half* __restrict__ A, const __half* __restrict__ A2, int rowsA,
    const uint32_t* __restrict__ WfHi, const uint32_t* __restrict__ WfLo,
    const float* __restrict__ bias,
    __half* __restrict__ C16, float* __restrict__ Cf)
{
    extern __shared__ __align__(16) char dsm[];
    const int tid  = threadIdx.x;
    const int lane = tid & 31;
    const int wid  = tid >> 5;
    const int wm   = wid >> 1;     // 0..3, 32 rows each
    const int wn   = wid & 1;      // 0..1, 64 cols each

    const int row0 = blockIdx.y * 128;
    const int col0 = blockIdx.x * 128;
    const int nfp0 = blockIdx.x * 8;

    const uint32_t base = smem_u32(dsm);
    float* s_bias = (float*)(dsm + 2 * STAGE_B);

    const __half* Ah = A;
    int rb = row0;
    if (A2 != nullptr && row0 >= rowsA) { Ah = A2; rb = row0 - rowsA; }
    const __half* Ag = Ah + (size_t)rb * K;

    if (tid < 128) s_bias[tid] = bias[col0 + tid];

    const int NC = K / 32;

    auto issue = [&](int c, int buf) {
        const uint32_t sb = base + buf * STAGE_B;
        // A plane: 128 rows x 32 f16 (64B data in 80B rows), 512 units
        #pragma unroll
        for (int i = 0; i < 2; i++) {
            int w = tid + i * 256;
            int m = w >> 2, uu = w & 3;
            CP_ASYNC16(sb + OFF_A + m * 80 + uu * 16,
                       Ag + (size_t)m * K + c * 32 + uu * 8);
        }
        // B planes: per plane 512 units [ks(2)][nfp(8)][lane(32)]
        #pragma unroll
        for (int i = 0; i < 2; i++) {   // ks = i
            size_t gi = ((((size_t)c * 2 + i) * 16 + nfp0 + (tid >> 5)) * 32
                         + (tid & 31)) * 4;
            CP_ASYNC16(sb + OFF_BHI + (i * 256 + tid) * 16, WfHi + gi);
        }
        #pragma unroll
        for (int i = 0; i < 2; i++) {
            size_t gi = ((((size_t)c * 2 + i) * 16 + nfp0 + (tid >> 5)) * 32
                         + (tid & 31)) * 4;
            CP_ASYNC16(sb + OFF_BLO + (i * 256 + tid) * 16, WfLo + gi);
        }
    };

    issue(0, 0);
    CP_COMMIT();
    CP_WAIT0();
    __syncthreads();

    float acc[2][8][4];
    #pragma unroll
    for (int mi = 0; mi < 2; mi++)
        #pragma unroll
        for (int ni = 0; ni < 8; ni++)
            #pragma unroll
            for (int j = 0; j < 4; j++) acc[mi][ni][j] = 0.0f;

    const uint32_t laddr = (uint32_t)((lane & 15) * 80 + (lane >> 4) * 16);

    for (int c = 0; c < NC; c++) {
        const int cur = c & 1;
        if (c + 1 < NC) { issue(c + 1, cur ^ 1); CP_COMMIT(); }
        const uint32_t sb = base + cur * STAGE_B;

        #pragma unroll
        for (int ks = 0; ks < 2; ks++) {
            uint32_t aF[2][4];
            #pragma unroll
            for (int mi = 0; mi < 2; mi++) {
                const uint32_t tileOff =
                    (uint32_t)((wm * 32 + mi * 16) * 80 + ks * 32) + laddr;
                ldsm4(aF[mi], sb + OFF_A + tileOff);
            }
            #pragma unroll
            for (int p = 0; p < 4; p++) {
                const uint32_t boff =
                    (uint32_t)(((ks * 8 + wn * 4 + p) * 32 + lane) * 16);
                uint32_t bh[4], bl[4];
                asm volatile("ld.shared.v4.b32 {%0,%1,%2,%3}, [%4];"
                             : "=r"(bh[0]), "=r"(bh[1]), "=r"(bh[2]), "=r"(bh[3])
                             : "r"(sb + OFF_BHI + boff));
                asm volatile("ld.shared.v4.b32 {%0,%1,%2,%3}, [%4];"
                             : "=r"(bl[0]), "=r"(bl[1]), "=r"(bl[2]), "=r"(bl[3])
                             : "r"(sb + OFF_BLO + boff));
                #pragma unroll
                for (int h = 0; h < 2; h++) {   // 2 n-frags per v4
                    const int ni = p * 2 + h;
                    #pragma unroll
                    for (int mi = 0; mi < 2; mi++) {
                        mma_f16(acc[mi][ni], aF[mi], bh[h * 2], bh[h * 2 + 1]);
                        mma_f16(acc[mi][ni], aF[mi], bl[h * 2], bl[h * 2 + 1]);
                    }
                }
            }
        }
        if (c + 1 < NC) { CP_WAIT0(); __syncthreads(); }
    }

    // ---- epilogue ----
    const int g8 = lane >> 2;
    const int tg = lane & 3;
    #pragma unroll
    for (int mi = 0; mi < 2; mi++) {
        const int m = row0 + wm * 32 + mi * 16 + g8;
        #pragma unroll
        for (int ni = 0; ni < 8; ni++) {
            const int nl = wn * 64 + ni * 8 + tg * 2;
            const float b0 = s_bias[nl], b1 = s_bias[nl + 1];
            float v0 = acc[mi][ni][0] + b0;
            float v1 = acc[mi][ni][1] + b1;
            float v2 = acc[mi][ni][2] + b0;
            float v3 = acc[mi][ni][3] + b1;
            if (RELU) {
                v0 = fmaxf(v0, 0.f); v1 = fmaxf(v1, 0.f);
                v2 = fmaxf(v2, 0.f); v3 = fmaxf(v3, 0.f);
            }
            const size_t i0 = (size_t)m * HDIM + col0 + nl;
            const size_t i1 = (size_t)(m + 8) * HDIM + col0 + nl;
            if (PACKOUT) {
                *(uint32_t*)(C16 + i0) =
                    pack2h(__float2half_rn(v0), __float2half_rn(v1));
                *(uint32_t*)(C16 + i1) =
                    pack2h(__float2half_rn(v2), __float2half_rn(v3));
            } else {
                *(float2*)(Cf + i0) = make_float2(v0, v1);
                *(float2*)(Cf + i1) = make_float2(v2, v3);
            }
        }
    }
}

// ---------------------------------------------------------------------------
// Launch
// ---------------------------------------------------------------------------
extern "C" void kernel_launch(void* const* d_in, const int* in_sizes, int n_in,
                              void* d_out, int out_size)
{
    const float *x = 0, *u = 0, *r = 0, *low = 0, *high = 0, *We0 = 0;
    const int* qptr = 0;
    const float* W65[8];  int nW = 0;
    const float* b256[8]; int nB = 0;

    for (int i = 0; i < n_in; i++) {
        int s = in_sizes[i];
        const float* p = (const float*)d_in[i];
        if (s == BROWS * MDIM) {
            if (!x) x = p; else if (!u) u = p; else if (!r) r = p;
        } else if (s == MDIM) {
            if (!low) low = p; else if (!high) high = p;
        } else if (s == 1) {
            qptr = (const int*)d_in[i];
        } else if (s == MDIM * HDIM) {
            We0 = p;
        } else if (s == HDIM * HDIM) {
            if (nW < 8) W65[nW++] = p;
        } else if (s == HDIM) {
            if (nB < 8) b256[nB++] = p;
        }
    }
    const float* bl[6] = {b256[0], b256[1], b256[2], b256[3], b256[4], b256[5]};

    __half *x16 = 0, *xc16 = 0, *a0 = 0, *a1 = 0;
    uint32_t *w0p = 0, *wHp = 0;
    cudaGetSymbolAddress((void**)&x16,  g_x16);
    cudaGetSymbolAddress((void**)&xc16, g_xc16);
    cudaGetSymbolAddress((void**)&a0,   g_a0);
    cudaGetSymbolAddress((void**)&a1,   g_a1);
    cudaGetSymbolAddress((void**)&w0p,  g_W0p);
    cudaGetSymbolAddress((void**)&wHp,  g_WHp);
    float* out = (float*)d_out;

    const size_t W0PL = (size_t)MDIM * 128;
    const size_t WHPL = (size_t)HDIM * 128;
    uint32_t* w0hi = w0p;
    uint32_t* w0lo = w0p + W0PL;
    auto whi = [&](int i) { return wHp + (size_t)i * 2 * WHPL; };
    auto wlo = [&](int i) { return wHp + (size_t)i * 2 * WHPL + WHPL; };

    cudaFuncSetAttribute(gemm_f16x2<MDIM, true,  true >, cudaFuncAttributeMaxDynamicSharedMemorySize, DSMEM_SZ);
    cudaFuncSetAttribute(gemm_f16x2<HDIM, true,  true >, cudaFuncAttributeMaxDynamicSharedMemorySize, DSMEM_SZ);
    cudaFuncSetAttribute(gemm_f16x2<HDIM, false, true >, cudaFuncAttributeMaxDynamicSharedMemorySize, DSMEM_SZ);
    cudaFuncSetAttribute(gemm_f16x2<HDIM, false, false>, cudaFuncAttributeMaxDynamicSharedMemorySize, DSMEM_SZ);

    // 1) corruption + fp16 emit
    corrupt_kernel<<<BROWS, 256>>>(x, u, r, low, high, qptr, 307, x16, xc16);

    // 2) weight split-packing (tiny)
    pack_w_kernel<<<(MDIM / 2 * HDIM) / 256, 256>>>(We0, w0hi, w0lo, MDIM);
    for (int i = 0; i < 5; i++)
        pack_w_kernel<<<(HDIM / 2 * HDIM) / 256, 256>>>(W65[i], whi(i), wlo(i), HDIM);

    // 3) 6 layers, fp16 split-2 tensor cores, both branches stacked
    dim3 grid(HDIM / 128, TOTROWS / 128);   // (2, 512)
    dim3 blk(256);
    const __half* NH = (const __half*)0;

    gemm_f16x2<MDIM, true,  true ><<<grid, blk, DSMEM_SZ>>>(
        x16, xc16, BROWS, w0hi, w0lo, bl[0], a0, (float*)0);
    gemm_f16x2<HDIM, true,  true ><<<grid, blk, DSMEM_SZ>>>(
        a0, NH, TOTROWS, whi(0), wlo(0), bl[1], a1, (float*)0);
    gemm_f16x2<HDIM, true,  true ><<<grid, blk, DSMEM_SZ>>>(
        a1, NH, TOTROWS, whi(1), wlo(1), bl[2], a0, (float*)0);
    gemm_f16x2<HDIM, false, true ><<<grid, blk, DSMEM_SZ>>>(
        a0, NH, TOTROWS, whi(2), wlo(2), bl[3], a1, (float*)0);
    gemm_f16x2<HDIM, true,  true ><<<grid, blk, DSMEM_SZ>>>(
        a1, NH, TOTROWS, whi(3), wlo(3), bl[4], a0, (float*)0);
    gemm_f16x2<HDIM, false, false><<<grid, blk, DSMEM_SZ>>>(
        a0, NH, TOTROWS, whi(4), wlo(4), bl[5], (__half*)0, out);

    (void)out_size;
}

// round 10
// speedup vs baseline: 3.6668x; 1.2389x over previous
#include <cuda_runtime.h>
#include <cuda_fp16.h>
#include <cstdint>

// Problem constants (fixed by the dataset)
#define BROWS   32768
#define MDIM    512
#define HDIM    256
#define TOTROWS (2 * BROWS)   // both branches stacked

// ---------------------------------------------------------------------------
// Scratch (static device allocations — no cudaMalloc allowed)
// ---------------------------------------------------------------------------
__device__ __align__(16) __half g_x16 [(size_t)BROWS * MDIM];
__device__ __align__(16) __half g_xc16[(size_t)BROWS * MDIM];
__device__ __align__(16) __half g_a0  [(size_t)TOTROWS * HDIM];
__device__ __align__(16) __half g_a1  [(size_t)TOTROWS * HDIM];
// Weights: fp16 fragment-major plane (u32 = 2 fp16 along k), v4-grouped pairs
__device__ __align__(16) uint32_t g_W0p[(size_t)MDIM * 128];
__device__ __align__(16) uint32_t g_WHp[5][(size_t)HDIM * 128];

// ---------------------------------------------------------------------------
// Helpers
// ---------------------------------------------------------------------------
__device__ __forceinline__ uint32_t smem_u32(const void* p) {
    uint32_t a;
    asm("{ .reg .u64 t; cvta.to.shared.u64 t, %1; cvt.u32.u64 %0, t; }"
        : "=r"(a) : "l"(p));
    return a;
}
__device__ __forceinline__ void mma_f16(float* d, const uint32_t* a,
                                        uint32_t b0, uint32_t b1) {
    asm volatile(
        "mma.sync.aligned.m16n8k16.row.col.f32.f16.f16.f32 "
        "{%0,%1,%2,%3}, {%4,%5,%6,%7}, {%8,%9}, {%0,%1,%2,%3};"
        : "+f"(d[0]), "+f"(d[1]), "+f"(d[2]), "+f"(d[3])
        : "r"(a[0]), "r"(a[1]), "r"(a[2]), "r"(a[3]), "r"(b0), "r"(b1));
}
__device__ __forceinline__ void ldsm4(uint32_t* r, uint32_t addr) {
    asm volatile("ldmatrix.sync.aligned.m8n8.x4.shared.b16 {%0,%1,%2,%3}, [%4];"
                 : "=r"(r[0]), "=r"(r[1]), "=r"(r[2]), "=r"(r[3]) : "r"(addr));
}
#define CP_ASYNC16(dst, src) \
    asm volatile("cp.async.cg.shared.global [%0], [%1], 16;" :: "r"(dst), "l"(src))
#define CP_COMMIT() asm volatile("cp.async.commit_group;" ::: "memory")
#define CP_WAIT0()  asm volatile("cp.async.wait_group 0;" ::: "memory")

__device__ __forceinline__ uint32_t pack2h(__half a, __half b) {
    return (uint32_t)__half_as_ushort(a) |
           ((uint32_t)__half_as_ushort(b) << 16);
}

// ---------------------------------------------------------------------------
// Corruption kernel (rank-q logic validated rel_err = 0.0 since R1);
// emits plain fp16 planes for x and xc.  (Byte-identical to R9.)
// ---------------------------------------------------------------------------
__global__ void __launch_bounds__(256) corrupt_kernel(
    const float* __restrict__ x, const float* __restrict__ u,
    const float* __restrict__ r, const float* __restrict__ low,
    const float* __restrict__ high, const int* __restrict__ qptr, int qdef,
    __half* __restrict__ x16, __half* __restrict__ xc16)
{
    __shared__ float us[MDIM];
    __shared__ int   hist[1024];
    __shared__ int   s_bin, s_rank, s_cnt;
    __shared__ unsigned long long cand[48];
    __shared__ unsigned long long s_thresh;

    const int row = blockIdx.x;
    const int tid = threadIdx.x;
    const size_t base = (size_t)row * MDIM;

    int q = qptr ? *qptr : qdef;

    for (int j = tid; j < MDIM; j += 256) us[j] = u[base + j];
    for (int j = tid; j < 1024; j += 256) hist[j] = 0;
    __syncthreads();

    if (q <= 0) {
        if (tid == 0) s_thresh = 0ULL;
    } else if (q >= MDIM) {
        if (tid == 0) s_thresh = ~0ULL;
    }

    if (q > 0 && q < MDIM) {
        for (int j = tid; j < MDIM; j += 256) {
            float v = us[j];
            int b = (int)(v * 1024.0f);
            b = b < 0 ? 0 : (b > 1023 ? 1023 : b);
            atomicAdd(&hist[b], 1);
        }
        __syncthreads();

        if (tid < 32) {
            int s = 0;
            const int b0 = tid * 32;
            #pragma unroll
            for (int b = 0; b < 32; b++) s += hist[b0 + b];
            int pre = s;
            #pragma unroll
            for (int o = 1; o < 32; o <<= 1) {
                int n = __shfl_up_sync(0xffffffffu, pre, o);
                if (tid >= o) pre += n;
            }
            int excl = pre - s;
            if (q >= excl && q < excl + s) {
                int c = excl;
                for (int b = b0; b < b0 + 32; b++) {
                    int h = hist[b];
                    if (q < c + h) { s_bin = b; s_rank = q - c; break; }
                    c += h;
                }
            }
            if (tid == 0) s_cnt = 0;
        }
        __syncthreads();

        const int bsel = s_bin;
        for (int j = tid; j < MDIM; j += 256) {
            float v = us[j];
            int b = (int)(v * 1024.0f);
            b = b < 0 ? 0 : (b > 1023 ? 1023 : b);
            if (b == bsel) {
                int idx = atomicAdd(&s_cnt, 1);
                if (idx < 48)
                    cand[idx] = ((unsigned long long)__float_as_uint(v) << 9)
                                | (unsigned)j;
            }
        }
        __syncthreads();

        if (tid == 0) {
            int cnt = s_cnt < 48 ? s_cnt : 48;
            int rk = s_rank;
            unsigned long long th = 0ULL;
            for (int i = 0; i < cnt; i++) {
                int c = 0;
                for (int k2 = 0; k2 < cnt; k2++) c += (cand[k2] < cand[i]);
                if (c == rk) th = cand[i];
            }
            s_thresh = th;
        }
    }
    __syncthreads();

    const unsigned long long th = s_thresh;
    const int j0 = tid * 2, j1 = j0 + 1;
    float v0 = us[j0], v1 = us[j1];
    unsigned long long k0 =
        ((unsigned long long)__float_as_uint(v0) << 9) | (unsigned)j0;
    unsigned long long k1 =
        ((unsigned long long)__float_as_uint(v1) << 9) | (unsigned)j1;
    float xv0 = x[base + j0], xv1 = x[base + j1];
    float xr0 = low[j0] + (high[j0] - low[j0]) * r[base + j0];
    float xr1 = low[j1] + (high[j1] - low[j1]) * r[base + j1];
    float xc0 = (k0 < th) ? xr0 : xv0;
    float xc1 = (k1 < th) ? xr1 : xv1;

    *(uint32_t*)(x16 + base + j0) =
        pack2h(__float2half_rn(xv0), __float2half_rn(xv1));
    *(uint32_t*)(xc16 + base + j0) =
        pack2h(__float2half_rn(xc0), __float2half_rn(xc1));
}

// ---------------------------------------------------------------------------
// Weight pack: W[K,256] -> fp16 B-fragment plane, v4-grouped.
// Geometry validated R5-R9: u32 idx = (((c*2+ks)*16+nfp)*32+lane)*4 + reg4
//   c=k/32, ks=(k/16)&1, rem=k%16: b01=rem/8, tig=(rem%8)/2 (k-pair, even low)
//   nf=n/8, nfp=nf/2, reg4=(nf&1)*2+b01, lane=(n%8)*4+tig
// ---------------------------------------------------------------------------
__global__ void __launch_bounds__(256) pack_w_kernel(
    const float* __restrict__ W, uint32_t* __restrict__ Wf, int K)
{
    int idx = blockIdx.x * 256 + threadIdx.x;   // over (K/2)*256
    if (idx >= (K / 2) * HDIM) return;
    int k2 = idx >> 8;
    int n  = idx & 255;
    int k  = k2 * 2;
    __half h0 = __float2half_rn(W[(size_t)k * HDIM + n]);
    __half h1 = __float2half_rn(W[(size_t)(k + 1) * HDIM + n]);

    int c = k >> 5, ks = (k >> 4) & 1, rem = k & 15;
    int b01 = rem >> 3, tig = (rem & 7) >> 1;
    int nf = n >> 3, nfp = nf >> 1;
    int reg4 = ((nf & 1) << 1) | b01;
    int lane = ((n & 7) << 2) | tig;
    size_t i32 = ((((size_t)c * 2 + ks) * 16 + nfp) * 32 + lane) * 4 + reg4;
    Wf[i32] = pack2h(h0, h1);
}

// ---------------------------------------------------------------------------
// fp16 GEMM: C[128x128 tile of 256] = A @ W + bias (single product).
// A: plain fp16 row-major. 1 MMA per m16n8k16 tile.
// 8 warps (4m x 2n), warp tile 32x64, BK=32, double-buffered cp.async,
// ldmatrix.x4 A (80B rows), lds.128 B (2 n-frags/load). (R9 geometry.)
// ---------------------------------------------------------------------------
#define OFF_A   0
#define OFF_B   10240
#define STAGE_B 18432
#define DSMEM_SZ (2 * STAGE_B + 512)

template <int K, bool RELU, bool PACKOUT>
__global__ void __launch_bounds__(256, 2) gemm_f16(
    const __half* __restrict__ A, const __half* __restrict__ A2, int rowsA,
    const uint32_t* __restrict__ Wf,
    const float* __restrict__ bias,
    __half* __restrict__ C16, float* __restrict__ Cf)
{
    extern __shared__ __align__(16) char dsm[];
    const int tid  = threadIdx.x;
    const int lane = tid & 31;
    const int wid  = tid >> 5;
    const int wm   = wid >> 1;     // 0..3, 32 rows each
    const int wn   = wid & 1;      // 0..1, 64 cols each

    const int row0 = blockIdx.y * 128;
    const int col0 = blockIdx.x * 128;
    const int nfp0 = blockIdx.x * 8;

    const uint32_t base = smem_u32(dsm);
    float* s_bias = (float*)(dsm + 2 * STAGE_B);

    const __half* Ah = A;
    int rb = row0;
    if (A2 != nullptr && row0 >= rowsA) { Ah = A2; rb = row0 - rowsA; }
    const __half* Ag = Ah + (size_t)rb * K;

    if (tid < 128) s_bias[tid] = bias[col0 + tid];

    const int NC = K / 32;

    auto issue = [&](int c, int buf) {
        const uint32_t sb = base + buf * STAGE_B;
        // A plane: 128 rows x 32 f16 (64B data in 80B rows), 512 units
        #pragma unroll
        for (int i = 0; i < 2; i++) {
            int w = tid + i * 256;
            int m = w >> 2, uu = w & 3;
            CP_ASYNC16(sb + OFF_A + m * 80 + uu * 16,
                       Ag + (size_t)m * K + c * 32 + uu * 8);
        }
        // B plane: 512 units [ks(2)][nfp(8)][lane(32)]
        #pragma unroll
        for (int i = 0; i < 2; i++) {   // ks = i
            size_t gi = ((((size_t)c * 2 + i) * 16 + nfp0 + (tid >> 5)) * 32
                         + (tid & 31)) * 4;
            CP_ASYNC16(sb + OFF_B + (i * 256 + tid) * 16, Wf + gi);
        }
    };

    issue(0, 0);
    CP_COMMIT();
    CP_WAIT0();
    __syncthreads();

    float acc[2][8][4];
    #pragma unroll
    for (int mi = 0; mi < 2; mi++)
        #pragma unroll
        for (int ni = 0; ni < 8; ni++)
            #pragma unroll
            for (int j = 0; j < 4; j++) acc[mi][ni][j] = 0.0f;

    const uint32_t laddr = (uint32_t)((lane & 15) * 80 + (lane >> 4) * 16);

    for (int c = 0; c < NC; c++) {
        const int cur = c & 1;
        if (c + 1 < NC) { issue(c + 1, cur ^ 1); CP_COMMIT(); }
        const uint32_t sb = base + cur * STAGE_B;

        #pragma unroll
        for (int ks = 0; ks < 2; ks++) {
            uint32_t aF[2][4];
            #pragma unroll
            for (int mi = 0; mi < 2; mi++) {
                const uint32_t tileOff =
                    (uint32_t)((wm * 32 + mi * 16) * 80 + ks * 32) + laddr;
                ldsm4(aF[mi], sb + OFF_A + tileOff);
            }
            #pragma unroll
            for (int p = 0; p < 4; p++) {
                const uint32_t boff =
                    (uint32_t)(((ks * 8 + wn * 4 + p) * 32 + lane) * 16);
                uint32_t bv[4];
                asm volatile("ld.shared.v4.b32 {%0,%1,%2,%3}, [%4];"
                             : "=r"(bv[0]), "=r"(bv[1]), "=r"(bv[2]), "=r"(bv[3])
                             : "r"(sb + OFF_B + boff));
                #pragma unroll
                for (int h = 0; h < 2; h++) {   // 2 n-frags per v4
                    const int ni = p * 2 + h;
                    #pragma unroll
                    for (int mi = 0; mi < 2; mi++)
                        mma_f16(acc[mi][ni], aF[mi], bv[h * 2], bv[h * 2 + 1]);
                }
            }
        }
        if (c + 1 < NC) { CP_WAIT0(); __syncthreads(); }
    }

    // ---- epilogue ----
    const int g8 = lane >> 2;
    const int tg = lane & 3;
    #pragma unroll
    for (int mi = 0; mi < 2; mi++) {
        const int m = row0 + wm * 32 + mi * 16 + g8;
        #pragma unroll
        for (int ni = 0; ni < 8; ni++) {
            const int nl = wn * 64 + ni * 8 + tg * 2;
            const float b0 = s_bias[nl], b1 = s_bias[nl + 1];
            float v0 = acc[mi][ni][0] + b0;
            float v1 = acc[mi][ni][1] + b1;
            float v2 = acc[mi][ni][2] + b0;
            float v3 = acc[mi][ni][3] + b1;
            if (RELU) {
                v0 = fmaxf(v0, 0.f); v1 = fmaxf(v1, 0.f);
                v2 = fmaxf(v2, 0.f); v3 = fmaxf(v3, 0.f);
            }
            const size_t i0 = (size_t)m * HDIM + col0 + nl;
            const size_t i1 = (size_t)(m + 8) * HDIM + col0 + nl;
            if (PACKOUT) {
                *(uint32_t*)(C16 + i0) =
                    pack2h(__float2half_rn(v0), __float2half_rn(v1));
                *(uint32_t*)(C16 + i1) =
                    pack2h(__float2half_rn(v2), __float2half_rn(v3));
            } else {
                *(float2*)(Cf + i0) = make_float2(v0, v1);
                *(float2*)(Cf + i1) = make_float2(v2, v3);
            }
        }
    }
}

// ---------------------------------------------------------------------------
// Launch
// ---------------------------------------------------------------------------
extern "C" void kernel_launch(void* const* d_in, const int* in_sizes, int n_in,
                              void* d_out, int out_size)
{
    const float *x = 0, *u = 0, *r = 0, *low = 0, *high = 0, *We0 = 0;
    const int* qptr = 0;
    const float* W65[8];  int nW = 0;
    const float* b256[8]; int nB = 0;

    for (int i = 0; i < n_in; i++) {
        int s = in_sizes[i];
        const float* p = (const float*)d_in[i];
        if (s == BROWS * MDIM) {
            if (!x) x = p; else if (!u) u = p; else if (!r) r = p;
        } else if (s == MDIM) {
            if (!low) low = p; else if (!high) high = p;
        } else if (s == 1) {
            qptr = (const int*)d_in[i];
        } else if (s == MDIM * HDIM) {
            We0 = p;
        } else if (s == HDIM * HDIM) {
            if (nW < 8) W65[nW++] = p;
        } else if (s == HDIM) {
            if (nB < 8) b256[nB++] = p;
        }
    }
    const float* bl[6] = {b256[0], b256[1], b256[2], b256[3], b256[4], b256[5]};

    __half *x16 = 0, *xc16 = 0, *a0 = 0, *a1 = 0;
    uint32_t *w0p = 0, *wHp = 0;
    cudaGetSymbolAddress((void**)&x16,  g_x16);
    cudaGetSymbolAddress((void**)&xc16, g_xc16);
    cudaGetSymbolAddress((void**)&a0,   g_a0);
    cudaGetSymbolAddress((void**)&a1,   g_a1);
    cudaGetSymbolAddress((void**)&w0p,  g_W0p);
    cudaGetSymbolAddress((void**)&wHp,  g_WHp);
    float* out = (float*)d_out;

    const size_t WHPL = (size_t)HDIM * 128;
    auto wf = [&](int i) { return wHp + (size_t)i * WHPL; };

    cudaFuncSetAttribute(gemm_f16<MDIM, true,  true >, cudaFuncAttributeMaxDynamicSharedMemorySize, DSMEM_SZ);
    cudaFuncSetAttribute(gemm_f16<HDIM, true,  true >, cudaFuncAttributeMaxDynamicSharedMemorySize, DSMEM_SZ);
    cudaFuncSetAttribute(gemm_f16<HDIM, false, true >, cudaFuncAttributeMaxDynamicSharedMemorySize, DSMEM_SZ);
    cudaFuncSetAttribute(gemm_f16<HDIM, false, false>, cudaFuncAttributeMaxDynamicSharedMemorySize, DSMEM_SZ);

    // 1) corruption + fp16 emit
    corrupt_kernel<<<BROWS, 256>>>(x, u, r, low, high, qptr, 307, x16, xc16);

    // 2) weight packing (tiny)
    pack_w_kernel<<<(MDIM / 2 * HDIM) / 256, 256>>>(We0, w0p, MDIM);
    for (int i = 0; i < 5; i++)
        pack_w_kernel<<<(HDIM / 2 * HDIM) / 256, 256>>>(W65[i], wf(i), HDIM);

    // 3) 6 layers, plain fp16 tensor cores, both branches stacked
    dim3 grid(HDIM / 128, TOTROWS / 128);   // (2, 512)
    dim3 blk(256);
    const __half* NH = (const __half*)0;

    gemm_f16<MDIM, true,  true ><<<grid, blk, DSMEM_SZ>>>(
        x16, xc16, BROWS, w0p, bl[0], a0, (float*)0);
    gemm_f16<HDIM, true,  true ><<<grid, blk, DSMEM_SZ>>>(
        a0, NH, TOTROWS, wf(0), bl[1], a1, (float*)0);
    gemm_f16<HDIM, true,  true ><<<grid, blk, DSMEM_SZ>>>(
        a1, NH, TOTROWS, wf(1), bl[2], a0, (float*)0);
    gemm_f16<HDIM, false, true ><<<grid, blk, DSMEM_SZ>>>(
        a0, NH, TOTROWS, wf(2), bl[3], a1, (float*)0);
    gemm_f16<HDIM, true,  true ><<<grid, blk, DSMEM_SZ>>>(
        a1, NH, TOTROWS, wf(3), bl[4], a0, (float*)0);
    gemm_f16<HDIM, false, false><<<grid, blk, DSMEM_SZ>>>(
        a0, NH, TOTROWS, wf(4), bl[5], (__half*)0, out);

    (void)out_size;
}